// round 3
// baseline (speedup 1.0000x reference)
#include <cuda_runtime.h>
#include <cstdint>

#define E_CNT   300000
#define MTILE   128
#define NTH     512
#define NCTA    ((E_CNT + MTILE - 1) / MTILE)

// ---- strides (floats) ----
#define SA1 36
#define SB1 264
#define SH  264
#define SB2 136
#define SOS 132

// ---- smem byte offsets ----
#define SM_IDX   0                  // 256 ints
#define SM_PAR   1024               // 640 floats
#define SM_B2    3584               // 3 x 32*136*4 = 52224
#define SM_U     55808
#define OFF_A1   0                  // 3 x 128*36*4  = 55296
#define OFF_B1   55296              // 3 x 32*264*4  = 101376 (ends 156672)
#define A1_BUF   18432
#define B1_BUF   33792
#define B2_BUF   17408
#define SM_TOTAL 212480             // 55808 + 156672

// pre-rounded (tf32) copies
__device__ float g_W1r[384 * 256];
__device__ float g_W2r[256 * 128];
__device__ float g_noder[50000 * 128];

static __device__ __forceinline__ uint32_t tf32r(float f) {
    uint32_t r; asm("cvt.rna.tf32.f32 %0, %1;" : "=r"(r) : "f"(f)); return r;
}
static __device__ __forceinline__ uint32_t smem_u32(const void* p) {
    uint32_t a;
    asm("{ .reg .u64 t; cvta.to.shared.u64 t, %1; cvt.u32.u64 %0, t; }" : "=r"(a) : "l"(p));
    return a;
}
static __device__ __forceinline__ void cp16(uint32_t dst, const void* src) {
    asm volatile("cp.async.cg.shared.global [%0], [%1], 16;" :: "r"(dst), "l"(src));
}
#define CP_COMMIT() asm volatile("cp.async.commit_group;" ::: "memory")
#define CP_WAIT(n)  asm volatile("cp.async.wait_group %0;" :: "n"(n) : "memory")

#define MMA_TF32(d, a, b)                                                     \
    asm volatile("mma.sync.aligned.m16n8k8.row.col.f32.tf32.tf32.f32 "        \
        "{%0,%1,%2,%3}, {%4,%5,%6,%7}, {%8,%9}, {%0,%1,%2,%3};"               \
        : "+f"((d)[0]), "+f"((d)[1]), "+f"((d)[2]), "+f"((d)[3])              \
        : "r"((a)[0]), "r"((a)[1]), "r"((a)[2]), "r"((a)[3]),                 \
          "r"((b)[0]), "r"((b)[1]))

// ---------------- prep: round weights + node table to tf32 ----------------
__global__ void prep_kernel(const float* __restrict__ W1,
                            const float* __restrict__ W2,
                            const float* __restrict__ nat) {
    int t = blockIdx.x * blockDim.x + threadIdx.x;
    int stride = gridDim.x * blockDim.x;
    const int NW1 = 384 * 256 / 4, NW2 = 256 * 128 / 4, NND = 50000 * 128 / 4;
    for (int i = t; i < NW1; i += stride) {
        float4 v = ((const float4*)W1)[i];
        uint4 u = { tf32r(v.x), tf32r(v.y), tf32r(v.z), tf32r(v.w) };
        ((uint4*)g_W1r)[i] = u;
    }
    for (int i = t; i < NW2; i += stride) {
        float4 v = ((const float4*)W2)[i];
        uint4 u = { tf32r(v.x), tf32r(v.y), tf32r(v.z), tf32r(v.w) };
        ((uint4*)g_W2r)[i] = u;
    }
    for (int i = t; i < NND; i += stride) {
        float4 v = ((const float4*)nat)[i];
        uint4 u = { tf32r(v.x), tf32r(v.y), tf32r(v.z), tf32r(v.w) };
        ((uint4*)g_noder)[i] = u;
    }
}

// ---------------- fused edge MLP ----------------
__global__ void __launch_bounds__(NTH, 1)
edge_mlp_kernel(const float* __restrict__ edge_attr,
                const int*   __restrict__ edge_index,
                const float* __restrict__ b1,
                const float* __restrict__ b2,
                const float* __restrict__ gamma_,
                const float* __restrict__ beta_,
                float* __restrict__ out)
{
    extern __shared__ char smem[];
    const uint32_t sb = smem_u32(smem);
    const int tid = threadIdx.x;
    const int wid = tid >> 5, lid = tid & 31;
    const int g = lid >> 2, t4 = lid & 3;
    const int ebase = blockIdx.x * MTILE;

    int*   sidx = (int*)(smem + SM_IDX);
    float* P    = (float*)(smem + SM_PAR);

    // params + gather indices
    if (tid < 256) {
        int r = tid & 127, half = tid >> 7;
        int e = ebase + r; if (e >= E_CNT) e = E_CNT - 1;
        sidx[half * 128 + r] = edge_index[half * E_CNT + e];
        P[tid] = b1[tid];
        if (tid < 128) {
            P[256 + tid] = b2[tid];
            P[384 + tid] = gamma_[tid];
            P[512 + tid] = beta_[tid];
        }
    }
    __syncthreads();

    const int mb  = (wid >> 2) * 32;   // 4 warps along M (tile 32)
    const int nb1 = (wid & 3) * 64;    // GEMM1: 4 warps along N (tile 64)
    const int nb2 = (wid & 3) * 32;    // GEMM2: tile 32

    auto issue1 = [&](int kc) {
        int buf = kc % 3;
        int src = kc >> 2, koff = (kc & 3) * 32;
        uint32_t abase = sb + SM_U + OFF_A1 + (uint32_t)buf * A1_BUF;
        uint32_t bbase = sb + SM_U + OFF_B1 + (uint32_t)buf * B1_BUF;
        #pragma unroll
        for (int i = 0; i < 2; i++) {
            int f = tid + i * NTH;
            int r = f >> 3, c4 = f & 7;
            const float* sp;
            if (src == 0)      sp = g_noder + (size_t)sidx[r] * 128 + koff;
            else if (src == 1) sp = g_noder + (size_t)sidx[128 + r] * 128 + koff;
            else { int e = ebase + r; if (e >= E_CNT) e = E_CNT - 1;
                   sp = edge_attr + (size_t)e * 128 + koff; }
            cp16(abase + (uint32_t)(r * SA1 + c4 * 4) * 4, sp + c4 * 4);
        }
        #pragma unroll
        for (int i = 0; i < 4; i++) {
            int f = tid + i * NTH;
            int k = f >> 6, n4 = f & 63;
            cp16(bbase + (uint32_t)(k * SB1 + n4 * 4) * 4,
                 g_W1r + (size_t)(kc * 32 + k) * 256 + n4 * 4);
        }
        CP_COMMIT();
    };
    auto issue2 = [&](int kc) {
        int buf = kc % 3;
        uint32_t bbase = sb + SM_B2 + (uint32_t)buf * B2_BUF;
        #pragma unroll
        for (int i = 0; i < 2; i++) {
            int f = tid + i * NTH;
            int k = f >> 5, n4 = f & 31;
            cp16(bbase + (uint32_t)(k * SB2 + n4 * 4) * 4,
                 g_W2r + (size_t)(kc * 32 + k) * 128 + n4 * 4);
        }
        CP_COMMIT();
    };

    // =================== GEMM1: H = relu(X @ W1 + b1) ===================
    float acc1[2][8][4];
    #pragma unroll
    for (int mi = 0; mi < 2; mi++)
        #pragma unroll
        for (int ni = 0; ni < 8; ni++)
            #pragma unroll
            for (int r = 0; r < 4; r++) acc1[mi][ni][r] = 0.0f;

    issue1(0); issue1(1);
    for (int kc = 0; kc < 12; kc++) {
        if (kc < 11) CP_WAIT(1); else CP_WAIT(0);
        __syncthreads();
        if (kc + 2 < 12) issue1(kc + 2);
        {
            const uint32_t* As = (const uint32_t*)(smem + SM_U + OFF_A1 + (kc % 3) * A1_BUF);
            const uint32_t* Bs = (const uint32_t*)(smem + SM_U + OFF_B1 + (kc % 3) * B1_BUF);
            #pragma unroll
            for (int ks = 0; ks < 4; ks++) {
                int k0 = ks * 8;
                uint32_t a[2][4];
                #pragma unroll
                for (int mi = 0; mi < 2; mi++) {
                    int m = mb + mi * 16 + g;
                    a[mi][0] = As[m * SA1 + k0 + t4];
                    a[mi][1] = As[(m + 8) * SA1 + k0 + t4];
                    a[mi][2] = As[m * SA1 + k0 + t4 + 4];
                    a[mi][3] = As[(m + 8) * SA1 + k0 + t4 + 4];
                }
                uint32_t b[8][2];
                #pragma unroll
                for (int ni = 0; ni < 8; ni++) {
                    int n = nb1 + ni * 8 + g;
                    b[ni][0] = Bs[(k0 + t4) * SB1 + n];
                    b[ni][1] = Bs[(k0 + t4 + 4) * SB1 + n];
                }
                #pragma unroll
                for (int mi = 0; mi < 2; mi++)
                    #pragma unroll
                    for (int ni = 0; ni < 8; ni++)
                        MMA_TF32(acc1[mi][ni], a[mi], b[ni]);
            }
        }
    }
    __syncthreads();

    // prefetch W2 chunks; write H (tf32) over A1/B1 region
    issue2(0); issue2(1);
    {
        float* Hs = (float*)(smem + SM_U);
        #pragma unroll
        for (int mi = 0; mi < 2; mi++) {
            #pragma unroll
            for (int ni = 0; ni < 8; ni++) {
                int k  = nb1 + ni * 8 + 2 * t4;
                int m0 = mb + mi * 16 + g;
                float v0 = fmaxf(acc1[mi][ni][0] + P[k],     0.0f);
                float v1 = fmaxf(acc1[mi][ni][1] + P[k + 1], 0.0f);
                float v2 = fmaxf(acc1[mi][ni][2] + P[k],     0.0f);
                float v3 = fmaxf(acc1[mi][ni][3] + P[k + 1], 0.0f);
                uint2 u0 = { tf32r(v0), tf32r(v1) };
                uint2 u1 = { tf32r(v2), tf32r(v3) };
                *(uint2*)&Hs[m0 * SH + k]       = u0;
                *(uint2*)&Hs[(m0 + 8) * SH + k] = u1;
            }
        }
    }
    __syncthreads();

    // =================== GEMM2: O = H @ W2 ===================
    float acc2[2][4][4];
    #pragma unroll
    for (int mi = 0; mi < 2; mi++)
        #pragma unroll
        for (int ni = 0; ni < 4; ni++)
            #pragma unroll
            for (int r = 0; r < 4; r++) acc2[mi][ni][r] = 0.0f;

    const uint32_t* Hsu = (const uint32_t*)(smem + SM_U);
    for (int kc = 0; kc < 8; kc++) {
        if (kc < 7) CP_WAIT(1); else CP_WAIT(0);
        __syncthreads();
        if (kc + 2 < 8) issue2(kc + 2);
        {
            const uint32_t* Bs = (const uint32_t*)(smem + SM_B2 + (kc % 3) * B2_BUF);
            #pragma unroll
            for (int ks = 0; ks < 4; ks++) {
                int k0 = kc * 32 + ks * 8;
                int kl = ks * 8;
                uint32_t a[2][4];
                #pragma unroll
                for (int mi = 0; mi < 2; mi++) {
                    int m = mb + mi * 16 + g;
                    a[mi][0] = Hsu[m * SH + k0 + t4];
                    a[mi][1] = Hsu[(m + 8) * SH + k0 + t4];
                    a[mi][2] = Hsu[m * SH + k0 + t4 + 4];
                    a[mi][3] = Hsu[(m + 8) * SH + k0 + t4 + 4];
                }
                uint32_t b[4][2];
                #pragma unroll
                for (int ni = 0; ni < 4; ni++) {
                    int n = nb2 + ni * 8 + g;
                    b[ni][0] = Bs[(kl + t4) * SB2 + n];
                    b[ni][1] = Bs[(kl + t4 + 4) * SB2 + n];
                }
                #pragma unroll
                for (int mi = 0; mi < 2; mi++)
                    #pragma unroll
                    for (int ni = 0; ni < 4; ni++)
                        MMA_TF32(acc2[mi][ni], a[mi], b[ni]);
            }
        }
    }
    __syncthreads();  // H dead; Os reuses region

    // =================== Epilogue: +b2, LayerNorm, store ===================
    float* Os = (float*)(smem + SM_U);
    #pragma unroll
    for (int mi = 0; mi < 2; mi++) {
        #pragma unroll
        for (int ni = 0; ni < 4; ni++) {
            int c  = nb2 + ni * 8 + 2 * t4;
            int m0 = mb + mi * 16 + g;
            *(float2*)&Os[m0 * SOS + c]       = make_float2(acc2[mi][ni][0], acc2[mi][ni][1]);
            *(float2*)&Os[(m0 + 8) * SOS + c] = make_float2(acc2[mi][ni][2], acc2[mi][ni][3]);
        }
    }
    __syncthreads();

    // LayerNorm: 4 threads per row, quad shuffle reduce
    {
        int row = tid >> 2, q = tid & 3;
        float vals[32];
        float sum = 0.0f, sq = 0.0f;
        #pragma unroll
        for (int c4 = 0; c4 < 8; c4++) {
            float4 v = *(float4*)&Os[row * SOS + q * 32 + c4 * 4];
            v.x += P[256 + q * 32 + c4 * 4 + 0];
            v.y += P[256 + q * 32 + c4 * 4 + 1];
            v.z += P[256 + q * 32 + c4 * 4 + 2];
            v.w += P[256 + q * 32 + c4 * 4 + 3];
            vals[c4 * 4 + 0] = v.x; vals[c4 * 4 + 1] = v.y;
            vals[c4 * 4 + 2] = v.z; vals[c4 * 4 + 3] = v.w;
            sum += v.x + v.y + v.z + v.w;
            sq  += v.x * v.x + v.y * v.y + v.z * v.z + v.w * v.w;
        }
        sum += __shfl_xor_sync(0xFFFFFFFF, sum, 1);
        sq  += __shfl_xor_sync(0xFFFFFFFF, sq,  1);
        sum += __shfl_xor_sync(0xFFFFFFFF, sum, 2);
        sq  += __shfl_xor_sync(0xFFFFFFFF, sq,  2);
        float mu  = sum * (1.0f / 128.0f);
        float var = sq * (1.0f / 128.0f) - mu * mu;
        float rs  = rsqrtf(var + 1e-5f);
        #pragma unroll
        for (int c4 = 0; c4 < 8; c4++) {
            float4 w;
            int cb = q * 32 + c4 * 4;
            w.x = (vals[c4 * 4 + 0] - mu) * rs * P[384 + cb + 0] + P[512 + cb + 0];
            w.y = (vals[c4 * 4 + 1] - mu) * rs * P[384 + cb + 1] + P[512 + cb + 1];
            w.z = (vals[c4 * 4 + 2] - mu) * rs * P[384 + cb + 2] + P[512 + cb + 2];
            w.w = (vals[c4 * 4 + 3] - mu) * rs * P[384 + cb + 3] + P[512 + cb + 3];
            *(float4*)&Os[row * SOS + cb] = w;
        }
    }
    __syncthreads();

    // coalesced float4 store
    {
        float4* o4 = (float4*)out;
        #pragma unroll
        for (int i = 0; i < 8; i++) {
            int f = tid + i * NTH;
            int row = f >> 5, c4 = f & 31;
            int e = ebase + row;
            if (e < E_CNT)
                o4[(size_t)e * 32 + c4] = *(float4*)&Os[row * SOS + c4 * 4];
        }
    }
}

extern "C" void kernel_launch(void* const* d_in, const int* in_sizes, int n_in,
                              void* d_out, int out_size) {
    const float* node_attr = (const float*)d_in[0];
    const float* edge_attr = (const float*)d_in[1];
    const int*   edge_idx  = (const int*)d_in[2];
    const float* W1 = (const float*)d_in[3];
    const float* b1 = (const float*)d_in[4];
    const float* W2 = (const float*)d_in[5];
    const float* b2 = (const float*)d_in[6];
    const float* g  = (const float*)d_in[7];
    const float* be = (const float*)d_in[8];
    float* out = (float*)d_out;

    prep_kernel<<<960, 256>>>(W1, W2, node_attr);

    cudaFuncSetAttribute(edge_mlp_kernel,
                         cudaFuncAttributeMaxDynamicSharedMemorySize, SM_TOTAL);
    edge_mlp_kernel<<<NCTA, NTH, SM_TOTAL>>>(edge_attr, edge_idx, b1, b2, g, be, out);
}

// round 4
// speedup vs baseline: 1.1584x; 1.1584x over previous
#include <cuda_runtime.h>
#include <cstdint>

#define E_CNT   300000
#define MTILE   128
#define NTH     256
#define NCTA    ((E_CNT + MTILE - 1) / MTILE)

// ---- strides (floats) ----
#define SA1  36     // A tile rows (k-major, 32 k + pad)
#define SB1T 36     // B1 n-major rows (32 k + pad)
#define SB2T 36
#define SH   260    // H rows (256 k + pad)
#define SOS  132

// ---- smem byte offsets ----
#define SM_IDX   0                  // 256 ints
#define SM_PAR   1024               // 640 floats -> ends 3584
#define SM_B2    3584               // 3 x 128*36*4 = 55296 -> ends 58880
#define SM_U     58880
#define OFF_A1   0                  // 3 x 128*36*4 = 55296
#define OFF_B1   55296              // 3 x 256*36*4 = 110592 -> ends 165888
#define A1_BUF   18432
#define B1_BUF   36864
#define B2_BUF   18432
#define SM_TOTAL 224768             // 58880 + 165888

// pre-rounded (tf32) copies; weights pre-TRANSPOSED to n-major
__device__ float g_W1t[256 * 384];   // [n][k]
__device__ float g_W2t[128 * 256];   // [n][k]
__device__ float g_noder[50000 * 128];

static __device__ __forceinline__ uint32_t tf32r(float f) {
    uint32_t r; asm("cvt.rna.tf32.f32 %0, %1;" : "=r"(r) : "f"(f)); return r;
}
static __device__ __forceinline__ uint32_t smem_u32(const void* p) {
    uint32_t a;
    asm("{ .reg .u64 t; cvta.to.shared.u64 t, %1; cvt.u32.u64 %0, t; }" : "=r"(a) : "l"(p));
    return a;
}
static __device__ __forceinline__ void cp16(uint32_t dst, const void* src) {
    asm volatile("cp.async.cg.shared.global [%0], [%1], 16;" :: "r"(dst), "l"(src));
}
#define CP_COMMIT() asm volatile("cp.async.commit_group;" ::: "memory")
#define CP_WAIT(n)  asm volatile("cp.async.wait_group %0;" :: "n"(n) : "memory")

#define LDSM4(r, addr)                                                        \
    asm volatile("ldmatrix.sync.aligned.m8n8.x4.shared.b16 {%0,%1,%2,%3}, [%4];" \
        : "=r"((r)[0]), "=r"((r)[1]), "=r"((r)[2]), "=r"((r)[3]) : "r"(addr))

#define MMA_TF32(d, a, b)                                                     \
    asm volatile("mma.sync.aligned.m16n8k8.row.col.f32.tf32.tf32.f32 "        \
        "{%0,%1,%2,%3}, {%4,%5,%6,%7}, {%8,%9}, {%0,%1,%2,%3};"               \
        : "+f"((d)[0]), "+f"((d)[1]), "+f"((d)[2]), "+f"((d)[3])              \
        : "r"((a)[0]), "r"((a)[1]), "r"((a)[2]), "r"((a)[3]),                 \
          "r"((b)[0]), "r"((b)[1]))

// ---------------- prep: tf32-round node table; round+transpose weights ----------------
__global__ void prep_kernel(const float* __restrict__ W1,
                            const float* __restrict__ W2,
                            const float* __restrict__ nat) {
    int t = blockIdx.x * blockDim.x + threadIdx.x;
    int stride = gridDim.x * blockDim.x;
    const int NW1 = 384 * 256, NW2 = 256 * 128, NND = 50000 * 128 / 4;
    for (int i = t; i < NW1; i += stride) {        // read coalesced along n
        int k = i >> 8, n = i & 255;
        ((uint32_t*)g_W1t)[n * 384 + k] = tf32r(W1[i]);
    }
    for (int i = t; i < NW2; i += stride) {
        int k = i >> 7, n = i & 127;
        ((uint32_t*)g_W2t)[n * 256 + k] = tf32r(W2[i]);
    }
    for (int i = t; i < NND; i += stride) {
        float4 v = ((const float4*)nat)[i];
        uint4 u = { tf32r(v.x), tf32r(v.y), tf32r(v.z), tf32r(v.w) };
        ((uint4*)g_noder)[i] = u;
    }
}

// ---------------- fused edge MLP ----------------
__global__ void __launch_bounds__(NTH, 1)
edge_mlp_kernel(const float* __restrict__ edge_attr,
                const int*   __restrict__ edge_index,
                const float* __restrict__ b1,
                const float* __restrict__ b2,
                const float* __restrict__ gamma_,
                const float* __restrict__ beta_,
                float* __restrict__ out)
{
    extern __shared__ char smem[];
    const uint32_t sb = smem_u32(smem);
    const int tid = threadIdx.x;
    const int wid = tid >> 5, lid = tid & 31;
    const int g = lid >> 2, t4 = lid & 3;
    const int ebase = blockIdx.x * MTILE;

    // ldmatrix per-thread row/col selectors (matrix id = lid>>3)
    const int sel = lid >> 3;
    const int arow = (sel & 1) * 8 + (lid & 7);   // A: row-half select
    const int acol = (sel >> 1) * 4;              // A: col-half select
    const int brow = (sel >> 1) * 8 + (lid & 7);  // B: n-half select
    const int bcol = (sel & 1) * 4;               // B: k-half select

    int*   sidx = (int*)(smem + SM_IDX);
    float* P    = (float*)(smem + SM_PAR);

    {
        int r = tid & 127, half = tid >> 7;
        int e = ebase + r; if (e >= E_CNT) e = E_CNT - 1;
        sidx[half * 128 + r] = edge_index[half * E_CNT + e];
        P[tid] = b1[tid];
        if (tid < 128) {
            P[256 + tid] = b2[tid];
            P[384 + tid] = gamma_[tid];
            P[512 + tid] = beta_[tid];
        }
    }
    __syncthreads();

    const int mb  = (wid >> 2) * 64;   // 2 warps along M (tile 64)
    const int nb1 = (wid & 3) * 64;    // GEMM1: 4 warps along N (tile 64)
    const int nb2 = (wid & 3) * 32;    // GEMM2: tile 32

    auto issue1 = [&](int kc) {
        int buf = kc % 3;
        int src = kc >> 2, koff = (kc & 3) * 32;
        uint32_t abase = sb + SM_U + OFF_A1 + (uint32_t)buf * A1_BUF;
        uint32_t bbase = sb + SM_U + OFF_B1 + (uint32_t)buf * B1_BUF;
        #pragma unroll
        for (int i = 0; i < 4; i++) {          // A: 128 rows x 8 chunks
            int f = tid + i * NTH;
            int r = f >> 3, c4 = f & 7;
            const float* sp;
            if (src == 0)      sp = g_noder + (size_t)sidx[r] * 128 + koff;
            else if (src == 1) sp = g_noder + (size_t)sidx[128 + r] * 128 + koff;
            else { int e = ebase + r; if (e >= E_CNT) e = E_CNT - 1;
                   sp = edge_attr + (size_t)e * 128 + koff; }
            cp16(abase + (uint32_t)(r * SA1 + c4 * 4) * 4, sp + c4 * 4);
        }
        #pragma unroll
        for (int i = 0; i < 8; i++) {          // B1t: 256 rows x 8 chunks
            int f = tid + i * NTH;
            int n = f >> 3, c4 = f & 7;
            cp16(bbase + (uint32_t)(n * SB1T + c4 * 4) * 4,
                 g_W1t + (size_t)n * 384 + kc * 32 + c4 * 4);
        }
        CP_COMMIT();
    };
    auto issue2 = [&](int kc) {
        int buf = kc % 3;
        uint32_t bbase = sb + SM_B2 + (uint32_t)buf * B2_BUF;
        #pragma unroll
        for (int i = 0; i < 4; i++) {          // B2t: 128 rows x 8 chunks
            int f = tid + i * NTH;
            int n = f >> 3, c4 = f & 7;
            cp16(bbase + (uint32_t)(n * SB2T + c4 * 4) * 4,
                 g_W2t + (size_t)n * 256 + kc * 32 + c4 * 4);
        }
        CP_COMMIT();
    };

    // =================== GEMM1: H = relu(X @ W1 + b1) ===================
    float acc1[4][8][4];
    #pragma unroll
    for (int mi = 0; mi < 4; mi++)
        #pragma unroll
        for (int ni = 0; ni < 8; ni++)
            #pragma unroll
            for (int r = 0; r < 4; r++) acc1[mi][ni][r] = 0.0f;

    issue1(0); issue1(1);
    for (int kc = 0; kc < 12; kc++) {
        if (kc < 11) CP_WAIT(1); else CP_WAIT(0);
        __syncthreads();
        if (kc + 2 < 12) issue1(kc + 2);
        {
            const uint32_t Ab = sb + SM_U + OFF_A1 + (uint32_t)(kc % 3) * A1_BUF;
            const uint32_t Bb = sb + SM_U + OFF_B1 + (uint32_t)(kc % 3) * B1_BUF;
            #pragma unroll
            for (int ks = 0; ks < 4; ks++) {
                int k0 = ks * 8;
                uint32_t a[4][4];
                #pragma unroll
                for (int mi = 0; mi < 4; mi++) {
                    uint32_t ad = Ab + (uint32_t)((mb + mi * 16 + arow) * SA1 + k0 + acol) * 4;
                    LDSM4(a[mi], ad);
                }
                uint32_t b[8][2];
                #pragma unroll
                for (int p = 0; p < 4; p++) {
                    uint32_t r4[4];
                    uint32_t bd = Bb + (uint32_t)((nb1 + p * 16 + brow) * SB1T + k0 + bcol) * 4;
                    LDSM4(r4, bd);
                    b[2 * p][0] = r4[0]; b[2 * p][1] = r4[1];
                    b[2 * p + 1][0] = r4[2]; b[2 * p + 1][1] = r4[3];
                }
                #pragma unroll
                for (int mi = 0; mi < 4; mi++)
                    #pragma unroll
                    for (int ni = 0; ni < 8; ni++)
                        MMA_TF32(acc1[mi][ni], a[mi], b[ni]);
            }
        }
    }
    __syncthreads();

    // prefetch W2; write H (tf32) over A1/B1 region
    issue2(0); issue2(1);
    {
        float* Hs = (float*)(smem + SM_U);
        #pragma unroll
        for (int mi = 0; mi < 4; mi++) {
            #pragma unroll
            for (int ni = 0; ni < 8; ni++) {
                int k  = nb1 + ni * 8 + 2 * t4;
                int m0 = mb + mi * 16 + g;
                float v0 = fmaxf(acc1[mi][ni][0] + P[k],     0.0f);
                float v1 = fmaxf(acc1[mi][ni][1] + P[k + 1], 0.0f);
                float v2 = fmaxf(acc1[mi][ni][2] + P[k],     0.0f);
                float v3 = fmaxf(acc1[mi][ni][3] + P[k + 1], 0.0f);
                uint2 u0 = { tf32r(v0), tf32r(v1) };
                uint2 u1 = { tf32r(v2), tf32r(v3) };
                *(uint2*)&Hs[m0 * SH + k]       = u0;
                *(uint2*)&Hs[(m0 + 8) * SH + k] = u1;
            }
        }
    }
    __syncthreads();

    // =================== GEMM2: O = H @ W2 ===================
    float acc2[4][4][4];
    #pragma unroll
    for (int mi = 0; mi < 4; mi++)
        #pragma unroll
        for (int ni = 0; ni < 4; ni++)
            #pragma unroll
            for (int r = 0; r < 4; r++) acc2[mi][ni][r] = 0.0f;

    const uint32_t Hb = sb + SM_U;
    for (int kc = 0; kc < 8; kc++) {
        if (kc < 7) CP_WAIT(1); else CP_WAIT(0);
        __syncthreads();
        if (kc + 2 < 8) issue2(kc + 2);
        {
            const uint32_t Bb = sb + SM_B2 + (uint32_t)(kc % 3) * B2_BUF;
            #pragma unroll
            for (int ks = 0; ks < 4; ks++) {
                int k0g = kc * 32 + ks * 8;
                int k0  = ks * 8;
                uint32_t a[4][4];
                #pragma unroll
                for (int mi = 0; mi < 4; mi++) {
                    uint32_t ad = Hb + (uint32_t)((mb + mi * 16 + arow) * SH + k0g + acol) * 4;
                    LDSM4(a[mi], ad);
                }
                uint32_t b[4][2];
                #pragma unroll
                for (int p = 0; p < 2; p++) {
                    uint32_t r4[4];
                    uint32_t bd = Bb + (uint32_t)((nb2 + p * 16 + brow) * SB2T + k0 + bcol) * 4;
                    LDSM4(r4, bd);
                    b[2 * p][0] = r4[0]; b[2 * p][1] = r4[1];
                    b[2 * p + 1][0] = r4[2]; b[2 * p + 1][1] = r4[3];
                }
                #pragma unroll
                for (int mi = 0; mi < 4; mi++)
                    #pragma unroll
                    for (int ni = 0; ni < 4; ni++)
                        MMA_TF32(acc2[mi][ni], a[mi], b[ni]);
            }
        }
    }
    __syncthreads();  // H dead; Os reuses region

    // =================== Epilogue: +b2, LayerNorm, store ===================
    float* Os = (float*)(smem + SM_U);
    #pragma unroll
    for (int mi = 0; mi < 4; mi++) {
        #pragma unroll
        for (int ni = 0; ni < 4; ni++) {
            int c  = nb2 + ni * 8 + 2 * t4;
            int m0 = mb + mi * 16 + g;
            *(float2*)&Os[m0 * SOS + c]       = make_float2(acc2[mi][ni][0], acc2[mi][ni][1]);
            *(float2*)&Os[(m0 + 8) * SOS + c] = make_float2(acc2[mi][ni][2], acc2[mi][ni][3]);
        }
    }
    __syncthreads();

    // LayerNorm: 2 threads per row
    {
        int row = tid >> 1, q = tid & 1;
        float vals[64];
        float sum = 0.0f, sq = 0.0f;
        #pragma unroll
        for (int c4 = 0; c4 < 16; c4++) {
            int cb = q * 64 + c4 * 4;
            float4 v = *(float4*)&Os[row * SOS + cb];
            v.x += P[256 + cb + 0]; v.y += P[256 + cb + 1];
            v.z += P[256 + cb + 2]; v.w += P[256 + cb + 3];
            vals[c4 * 4 + 0] = v.x; vals[c4 * 4 + 1] = v.y;
            vals[c4 * 4 + 2] = v.z; vals[c4 * 4 + 3] = v.w;
            sum += v.x + v.y + v.z + v.w;
            sq  += v.x * v.x + v.y * v.y + v.z * v.z + v.w * v.w;
        }
        sum += __shfl_xor_sync(0xFFFFFFFF, sum, 1);
        sq  += __shfl_xor_sync(0xFFFFFFFF, sq,  1);
        float mu  = sum * (1.0f / 128.0f);
        float var = sq * (1.0f / 128.0f) - mu * mu;
        float rs  = rsqrtf(var + 1e-5f);
        #pragma unroll
        for (int c4 = 0; c4 < 16; c4++) {
            int cb = q * 64 + c4 * 4;
            float4 w;
            w.x = (vals[c4 * 4 + 0] - mu) * rs * P[384 + cb + 0] + P[512 + cb + 0];
            w.y = (vals[c4 * 4 + 1] - mu) * rs * P[384 + cb + 1] + P[512 + cb + 1];
            w.z = (vals[c4 * 4 + 2] - mu) * rs * P[384 + cb + 2] + P[512 + cb + 2];
            w.w = (vals[c4 * 4 + 3] - mu) * rs * P[384 + cb + 3] + P[512 + cb + 3];
            *(float4*)&Os[row * SOS + cb] = w;
        }
    }
    __syncthreads();

    // coalesced float4 store
    {
        float4* o4 = (float4*)out;
        #pragma unroll
        for (int i = 0; i < 16; i++) {
            int f = tid + i * NTH;
            int row = f >> 5, c4 = f & 31;
            int e = ebase + row;
            if (e < E_CNT)
                o4[(size_t)e * 32 + c4] = *(float4*)&Os[row * SOS + c4 * 4];
        }
    }
}

extern "C" void kernel_launch(void* const* d_in, const int* in_sizes, int n_in,
                              void* d_out, int out_size) {
    const float* node_attr = (const float*)d_in[0];
    const float* edge_attr = (const float*)d_in[1];
    const int*   edge_idx  = (const int*)d_in[2];
    const float* W1 = (const float*)d_in[3];
    const float* b1 = (const float*)d_in[4];
    const float* W2 = (const float*)d_in[5];
    const float* b2 = (const float*)d_in[6];
    const float* g  = (const float*)d_in[7];
    const float* be = (const float*)d_in[8];
    float* out = (float*)d_out;

    prep_kernel<<<960, 256>>>(W1, W2, node_attr);

    cudaFuncSetAttribute(edge_mlp_kernel,
                         cudaFuncAttributeMaxDynamicSharedMemorySize, SM_TOTAL);
    edge_mlp_kernel<<<NCTA, NTH, SM_TOTAL>>>(edge_attr, edge_idx, b1, b2, g, be, out);
}